// round 6
// baseline (speedup 1.0000x reference)
#include <cuda_runtime.h>
#include <math.h>

#define N_NODES 50000
#define N_EDGES 800000
#define D 128
#define HEADS 8
#define UNITS 16
#define PAD 96                 // max supported in-degree (Poisson(16): P(>=96) ~ 1e-40)

// ---------------- device scratch ----------------
__device__ float g_xp[N_NODES * D];          // 25.6 MB
__device__ int   g_cnt[N_NODES];             // in-degree counters (zero-init; self-cleaning)
__device__ int   g_esrc[N_NODES * PAD];      // 19.2 MB padded CSR slots

__device__ __forceinline__ float lrelu(float v) {
    return fmaxf(v, 0.2f * v);               // branchless: valid since 0.2 < 1
}

// ---------------- kernel 1: xp = x @ W ----------------
// 128 threads/block, 16 nodes/block; thread t owns output column t.
// Inner loop processes 4 d's per step with float4 LDS: FMA-dominated issue mix.
__global__ void gemm_kernel(const float* __restrict__ x, const float* __restrict__ W) {
    __shared__ float xs[16][D];
    int node0 = blockIdx.x * 16;
    int t = threadIdx.x;

    #pragma unroll
    for (int m = 0; m < 16; m++)
        xs[m][t] = x[(node0 + m) * D + t];          // grid exactly covers 50000
    __syncthreads();

    float acc[16];
    #pragma unroll
    for (int m = 0; m < 16; m++) acc[m] = 0.0f;

    const float4* xs4 = (const float4*)&xs[0][0];   // [16][32]

    #pragma unroll 4
    for (int d4 = 0; d4 < D / 4; d4++) {
        float w0 = W[(4 * d4 + 0) * D + t];
        float w1 = W[(4 * d4 + 1) * D + t];
        float w2 = W[(4 * d4 + 2) * D + t];
        float w3 = W[(4 * d4 + 3) * D + t];
        #pragma unroll
        for (int m = 0; m < 16; m++) {
            float4 xv = xs4[m * (D / 4) + d4];      // LDS.128, warp-broadcast
            acc[m] += xv.x * w0 + xv.y * w1 + xv.z * w2 + xv.w * w3;
        }
    }

    #pragma unroll
    for (int m = 0; m < 16; m++)
        g_xp[(node0 + m) * D + t] = acc[m];
}

// ---------------- kernel 2: scatter sources into per-target padded slots ----------------
__global__ void fill_kernel(const int* __restrict__ edges) {
    int i = blockIdx.x * blockDim.x + threadIdx.x;
    if (i >= N_EDGES / 2) return;
    int4 e = ((const int4*)edges)[i];               // 2 edges per int4
    int p0 = atomicAdd(&g_cnt[e.y], 1);
    if (p0 < PAD) g_esrc[e.y * PAD + p0] = e.x;
    int p1 = atomicAdd(&g_cnt[e.w], 1);
    if (p1 < PAD) g_esrc[e.w * PAD + p1] = e.z;
}

// ---------------- kernel 3: fused GAT pass, warp per target (R3-proven loop) ----------------
__global__ void gat_kernel(const float* __restrict__ ka,
                           const float* __restrict__ ba,
                           const float* __restrict__ bias,
                           float* __restrict__ out) {
    int t = blockIdx.x * (blockDim.x >> 5) + (threadIdx.x >> 5);
    if (t >= N_NODES) return;
    int lane = threadIdx.x & 31;

    int deg = g_cnt[t];
    if (lane == 0) g_cnt[t] = 0;                    // self-clean for next replay
    deg = min(deg, PAD);
    const int* __restrict__ srcs = g_esrc + t * PAD;

    float4 k4  = ((const float4*)ka)[lane];
    float4 ba4 = ((const float4*)ba)[lane];
    float4 tb  = ((const float4*)(g_xp + (size_t)t * D))[lane];
    tb.x += 2.0f * ba4.x; tb.y += 2.0f * ba4.y;
    tb.z += 2.0f * ba4.z; tb.w += 2.0f * ba4.w;

    float4 acc = make_float4(0.0f, 0.0f, 0.0f, 0.0f);
    float wsum = 0.0f;

    // 1-ahead software pipeline with direct index loads (R3 form)
    float4 a, a_nxt;
    int src0 = (deg > 0) ? srcs[0] : 0;
    if (deg > 0) a_nxt = ((const float4*)(g_xp + (size_t)src0 * D))[lane];

    for (int i = 0; i < deg; i++) {
        a = a_nxt;
        if (i + 1 < deg) {
            int s = srcs[i + 1];
            a_nxt = ((const float4*)(g_xp + (size_t)s * D))[lane];
        }

        float p = lrelu(a.x + tb.x) * k4.x
                + lrelu(a.y + tb.y) * k4.y
                + lrelu(a.z + tb.z) * k4.z
                + lrelu(a.w + tb.w) * k4.w;
        p += __shfl_xor_sync(0xffffffffu, p, 1);
        p += __shfl_xor_sync(0xffffffffu, p, 2);

        float w = __expf(p);
        wsum  += w;
        acc.x += w * a.x; acc.y += w * a.y;
        acc.z += w * a.z; acc.w += w * a.w;
    }

    float inv = 1.0f / (wsum + 1e-7f);
    float4 b4 = ((const float4*)bias)[lane];
    float v[4] = { acc.x * inv + b4.x, acc.y * inv + b4.y,
                   acc.z * inv + b4.z, acc.w * inv + b4.w };
    #pragma unroll
    for (int j = 0; j < 4; j++) {
        float u = v[j];
        float c = 0.7978845608028654f * (u + 0.044715f * u * u * u);
        v[j] = 0.5f * u * (1.0f + tanhf(c));
    }
    ((float4*)(out + (size_t)t * D))[lane] = make_float4(v[0], v[1], v[2], v[3]);
}

// ---------------- launch ----------------
extern "C" void kernel_launch(void* const* d_in, const int* in_sizes, int n_in,
                              void* d_out, int out_size) {
    const float* x     = (const float*)d_in[0];
    const int*   edges = (const int*)  d_in[1];
    const float* W     = (const float*)d_in[2];
    const float* ka    = (const float*)d_in[3];
    const float* ba    = (const float*)d_in[4];
    const float* bias  = (const float*)d_in[5];
    float* out = (float*)d_out;

    (void)in_sizes; (void)n_in; (void)out_size;

    gemm_kernel<<<N_NODES / 16, 128>>>(x, W);
    fill_kernel<<<(N_EDGES / 2 + 255) / 256, 256>>>(edges);
    gat_kernel<<<(N_NODES + 7) / 8, 256>>>(ka, ba, bias, out);
}

// round 7
// speedup vs baseline: 1.2911x; 1.2911x over previous
#include <cuda_runtime.h>
#include <math.h>

#define N_NODES 50000
#define N_EDGES 800000
#define D 128
#define HEADS 8
#define UNITS 16

#define GEMM_BLOCKS 3125        // 50000 / 16 nodes per block
#define HIST_BLOCKS 392

// ---------------- device scratch (zero-initialized at load) ----------------
__device__ float g_xp[N_NODES * D];      // 25.6 MB
__device__ int   g_deg[N_NODES];         // degree per target (self-cleaning: gat resets)
__device__ int   g_off[N_NODES];         // start of target's region in g_esrc
__device__ int   g_cur[N_NODES];         // bump cursor for fill (rewritten each run)
__device__ int   g_esrc[N_EDGES];        // sources grouped by target (compact CSR)
__device__ int   g_total;                // bump allocator (reset by build_kernel)

__device__ __forceinline__ float lrelu(float v) {
    return fmaxf(v, 0.2f * v);
}

// ---------------- kernel 1: gemm (register-tiled) || hist ----------------
__global__ void build_kernel(const float* __restrict__ x, const float* __restrict__ W,
                             const int* __restrict__ edges) {
    if (blockIdx.x < GEMM_BLOCKS) {
        // xp = x @ W : 16 nodes/block, 128 threads.
        // thread: cg = tid&31 -> cols [4cg,4cg+4), ng = tid>>5 -> nodes [4ng,4ng+4)
        __shared__ float xs[16][D];
        int node0 = blockIdx.x * 16;
        int tid = threadIdx.x;
        int cg = tid & 31;
        int ng = tid >> 5;

        #pragma unroll
        for (int m = 0; m < 16; m++)
            xs[m][tid] = x[(node0 + m) * D + tid];
        __syncthreads();

        const float4* W4 = (const float4*)W;     // W4[k*32 + cg] = W[k][4cg..4cg+3]
        float4 acc0 = make_float4(0.f, 0.f, 0.f, 0.f);
        float4 acc1 = acc0, acc2 = acc0, acc3 = acc0;

        #pragma unroll 8
        for (int k = 0; k < D; k++) {
            float4 w4 = W4[k * 32 + cg];         // LDG.128, L1-resident (W = 64KB)
            float x0 = xs[4 * ng + 0][k];        // broadcast LDS
            float x1 = xs[4 * ng + 1][k];
            float x2 = xs[4 * ng + 2][k];
            float x3 = xs[4 * ng + 3][k];
            acc0.x += x0 * w4.x; acc0.y += x0 * w4.y; acc0.z += x0 * w4.z; acc0.w += x0 * w4.w;
            acc1.x += x1 * w4.x; acc1.y += x1 * w4.y; acc1.z += x1 * w4.z; acc1.w += x1 * w4.w;
            acc2.x += x2 * w4.x; acc2.y += x2 * w4.y; acc2.z += x2 * w4.z; acc2.w += x2 * w4.w;
            acc3.x += x3 * w4.x; acc3.y += x3 * w4.y; acc3.z += x3 * w4.z; acc3.w += x3 * w4.w;
        }

        float4* out4 = (float4*)(g_xp + (size_t)(node0 + 4 * ng) * D);
        out4[0 * 32 + cg] = acc0;                // 512B coalesced per warp
        out4[1 * 32 + cg] = acc1;
        out4[2 * 32 + cg] = acc2;
        out4[3 * 32 + cg] = acc3;
    } else {
        // hist: degree histogram over targets (grid-stride)
        if (blockIdx.x == GEMM_BLOCKS && threadIdx.x == 0) g_total = 0;
        int tid = (blockIdx.x - GEMM_BLOCKS) * 128 + threadIdx.x;
        int nthreads = HIST_BLOCKS * 128;
        const int4* e4 = (const int4*)edges;     // 2 edges per int4
        for (int i = tid; i < N_EDGES / 2; i += nthreads) {
            int4 e = e4[i];
            atomicAdd(&g_deg[e.y], 1);
            atomicAdd(&g_deg[e.w], 1);
        }
    }
}

// ---------------- kernel 2: offsets via warp-aggregated bump alloc (R3) ----------------
__global__ void offsets_kernel() {
    int t = blockIdx.x * blockDim.x + threadIdx.x;
    int lane = threadIdx.x & 31;
    int deg = (t < N_NODES) ? g_deg[t] : 0;

    int incl = deg;
    #pragma unroll
    for (int d = 1; d < 32; d <<= 1) {
        int v = __shfl_up_sync(0xffffffffu, incl, d);
        if (lane >= d) incl += v;
    }
    int total = __shfl_sync(0xffffffffu, incl, 31);
    int base = 0;
    if (lane == 31) base = atomicAdd(&g_total, total);
    base = __shfl_sync(0xffffffffu, base, 31);

    if (t < N_NODES) {
        int off = base + incl - deg;
        g_off[t] = off;
        g_cur[t] = off;
    }
}

// ---------------- kernel 3: scatter sources into per-target regions (R3) ----------------
__global__ void fill_kernel(const int* __restrict__ edges) {
    int e = blockIdx.x * blockDim.x + threadIdx.x;
    if (e >= N_EDGES) return;
    int2 ed = ((const int2*)edges)[e];
    int pos = atomicAdd(&g_cur[ed.y], 1);
    g_esrc[pos] = ed.x;
}

// ---------------- kernel 4: fused GAT pass, warp per target (R3-verbatim loop) ----------------
__global__ void gat_kernel(const float* __restrict__ ka,
                           const float* __restrict__ ba,
                           const float* __restrict__ bias,
                           float* __restrict__ out) {
    int t = blockIdx.x * (blockDim.x >> 5) + (threadIdx.x >> 5);
    if (t >= N_NODES) return;
    int lane = threadIdx.x & 31;

    int off = g_off[t];
    int deg = g_deg[t];
    if (lane == 0) g_deg[t] = 0;                 // self-clean for next replay

    float4 k4  = ((const float4*)ka)[lane];
    float4 ba4 = ((const float4*)ba)[lane];
    float4 tb  = ((const float4*)(g_xp + (size_t)t * D))[lane];
    tb.x += 2.0f * ba4.x; tb.y += 2.0f * ba4.y;
    tb.z += 2.0f * ba4.z; tb.w += 2.0f * ba4.w;

    float4 acc = make_float4(0.0f, 0.0f, 0.0f, 0.0f);
    float wsum = 0.0f;

    float4 a, a_nxt;
    int src_nxt = (deg > 0) ? g_esrc[off] : 0;
    if (deg > 0) a_nxt = ((const float4*)(g_xp + (size_t)src_nxt * D))[lane];

    for (int i = 0; i < deg; i++) {
        a = a_nxt;
        if (i + 1 < deg) {
            int s = g_esrc[off + i + 1];
            a_nxt = ((const float4*)(g_xp + (size_t)s * D))[lane];
        }

        float p = lrelu(a.x + tb.x) * k4.x
                + lrelu(a.y + tb.y) * k4.y
                + lrelu(a.z + tb.z) * k4.z
                + lrelu(a.w + tb.w) * k4.w;
        p += __shfl_xor_sync(0xffffffffu, p, 1);
        p += __shfl_xor_sync(0xffffffffu, p, 2);

        float w = __expf(p);
        wsum  += w;
        acc.x += w * a.x; acc.y += w * a.y;
        acc.z += w * a.z; acc.w += w * a.w;
    }

    float inv = 1.0f / (wsum + 1e-7f);
    float4 b4 = ((const float4*)bias)[lane];
    float v[4] = { acc.x * inv + b4.x, acc.y * inv + b4.y,
                   acc.z * inv + b4.z, acc.w * inv + b4.w };
    #pragma unroll
    for (int j = 0; j < 4; j++) {
        float u = v[j];
        float c = 0.7978845608028654f * (u + 0.044715f * u * u * u);
        v[j] = 0.5f * u * (1.0f + tanhf(c));
    }
    ((float4*)(out + (size_t)t * D))[lane] = make_float4(v[0], v[1], v[2], v[3]);
}

// ---------------- launch ----------------
extern "C" void kernel_launch(void* const* d_in, const int* in_sizes, int n_in,
                              void* d_out, int out_size) {
    const float* x     = (const float*)d_in[0];
    const int*   edges = (const int*)  d_in[1];
    const float* W     = (const float*)d_in[2];
    const float* ka    = (const float*)d_in[3];
    const float* ba    = (const float*)d_in[4];
    const float* bias  = (const float*)d_in[5];
    float* out = (float*)d_out;

    (void)in_sizes; (void)n_in; (void)out_size;

    build_kernel<<<GEMM_BLOCKS + HIST_BLOCKS, 128>>>(x, W, edges);
    offsets_kernel<<<(N_NODES + 255) / 256, 256>>>();
    fill_kernel<<<(N_EDGES + 255) / 256, 256>>>(edges);
    gat_kernel<<<(N_NODES + 7) / 8, 256>>>(ka, ba, bias, out);
}

// round 8
// speedup vs baseline: 1.7892x; 1.3858x over previous
#include <cuda_runtime.h>
#include <math.h>

#define N_NODES 50000
#define N_EDGES 800000
#define D 128
#define HEADS 8
#define UNITS 16

// ---------------- device scratch (zero-initialized at load) ----------------
__device__ float g_xp[N_NODES * D];      // 25.6 MB
__device__ int   g_deg[N_NODES];         // degree per target (self-cleaning: gat resets)
__device__ int   g_off[N_NODES];         // start of target's region in g_esrc
__device__ int   g_cur[N_NODES];         // bump cursor for fill
__device__ int   g_esrc[N_EDGES];        // sources grouped by target (compact CSR)
__device__ int   g_total;                // bump allocator (reset by hist_kernel)

__device__ __forceinline__ float lrelu(float v) {
    return fmaxf(v, 0.2f * v);
}

// ---------------- kernel 1: xp = x @ W (R3-exact) ----------------
__global__ void gemm_kernel(const float* __restrict__ x, const float* __restrict__ W) {
    __shared__ float xs[16][D];
    int node0 = blockIdx.x * 16;
    int t = threadIdx.x;

    #pragma unroll
    for (int m = 0; m < 16; m++) {
        int n = node0 + m;
        xs[m][t] = (n < N_NODES) ? x[n * D + t] : 0.0f;
    }
    __syncthreads();

    float acc[16];
    #pragma unroll
    for (int m = 0; m < 16; m++) acc[m] = 0.0f;

    #pragma unroll 4
    for (int d = 0; d < D; d++) {
        float w = W[d * D + t];
        #pragma unroll
        for (int m = 0; m < 16; m++) acc[m] += xs[m][d] * w;
    }

    #pragma unroll
    for (int m = 0; m < 16; m++) {
        int n = node0 + m;
        if (n < N_NODES) g_xp[n * D + t] = acc[m];
    }
}

// ---------------- kernel 2: degree histogram (R3-exact + g_total reset) ----------------
__global__ void hist_kernel(const int* __restrict__ edges) {
    if (blockIdx.x == 0 && threadIdx.x == 0) g_total = 0;   // consumed by next launch only
    int e = blockIdx.x * blockDim.x + threadIdx.x;
    if (e >= N_EDGES) return;
    int tgt = edges[2 * e + 1];
    atomicAdd(&g_deg[tgt], 1);
}

// ---------------- kernel 3: offsets via warp-aggregated bump alloc (R3-exact) ----------------
__global__ void offsets_kernel() {
    int t = blockIdx.x * blockDim.x + threadIdx.x;
    int lane = threadIdx.x & 31;
    int deg = (t < N_NODES) ? g_deg[t] : 0;

    int incl = deg;
    #pragma unroll
    for (int d = 1; d < 32; d <<= 1) {
        int v = __shfl_up_sync(0xffffffffu, incl, d);
        if (lane >= d) incl += v;
    }
    int total = __shfl_sync(0xffffffffu, incl, 31);
    int base = 0;
    if (lane == 31) base = atomicAdd(&g_total, total);
    base = __shfl_sync(0xffffffffu, base, 31);

    if (t < N_NODES) {
        int off = base + incl - deg;
        g_off[t] = off;
        g_cur[t] = off;
    }
}

// ---------------- kernel 4: scatter sources into per-target regions (R3-exact) ----------------
__global__ void fill_kernel(const int* __restrict__ edges) {
    int e = blockIdx.x * blockDim.x + threadIdx.x;
    if (e >= N_EDGES) return;
    int2 ed = ((const int2*)edges)[e];
    int pos = atomicAdd(&g_cur[ed.y], 1);
    g_esrc[pos] = ed.x;
}

// ---------------- kernel 5: fused GAT pass, warp per target ----------------
// Change vs R3: 2-deep branch-free software pipeline (clamped prefetch indices).
__global__ void gat_kernel(const float* __restrict__ ka,
                           const float* __restrict__ ba,
                           const float* __restrict__ bias,
                           float* __restrict__ out) {
    int t = blockIdx.x * (blockDim.x >> 5) + (threadIdx.x >> 5);
    if (t >= N_NODES) return;
    int lane = threadIdx.x & 31;

    int off = g_off[t];
    int deg = g_deg[t];
    if (lane == 0) g_deg[t] = 0;                 // self-clean for next replay

    float4 k4  = ((const float4*)ka)[lane];
    float4 ba4 = ((const float4*)ba)[lane];
    float4 tb  = ((const float4*)(g_xp + (size_t)t * D))[lane];
    tb.x += 2.0f * ba4.x; tb.y += 2.0f * ba4.y;
    tb.z += 2.0f * ba4.z; tb.w += 2.0f * ba4.w;

    float4 acc = make_float4(0.0f, 0.0f, 0.0f, 0.0f);
    float wsum = 0.0f;

    if (deg > 0) {
        int last = deg - 1;
        const int* __restrict__ srcs = g_esrc + off;

        // 2-deep pipeline: load for iteration i issued at i-2; tail loads clamped (unused)
        float4 a0 = ((const float4*)(g_xp + (size_t)srcs[0] * D))[lane];
        float4 a1 = ((const float4*)(g_xp + (size_t)srcs[min(1, last)] * D))[lane];

        for (int i = 0; i < deg; i++) {
            float4 cur = a0;
            a0 = a1;
            int s = srcs[min(i + 2, last)];
            a1 = ((const float4*)(g_xp + (size_t)s * D))[lane];

            float p = lrelu(cur.x + tb.x) * k4.x
                    + lrelu(cur.y + tb.y) * k4.y
                    + lrelu(cur.z + tb.z) * k4.z
                    + lrelu(cur.w + tb.w) * k4.w;
            p += __shfl_xor_sync(0xffffffffu, p, 1);
            p += __shfl_xor_sync(0xffffffffu, p, 2);

            float w = __expf(p);
            wsum  += w;
            acc.x += w * cur.x; acc.y += w * cur.y;
            acc.z += w * cur.z; acc.w += w * cur.w;
        }
    }

    float inv = 1.0f / (wsum + 1e-7f);
    float4 b4 = ((const float4*)bias)[lane];
    float v[4] = { acc.x * inv + b4.x, acc.y * inv + b4.y,
                   acc.z * inv + b4.z, acc.w * inv + b4.w };
    #pragma unroll
    for (int j = 0; j < 4; j++) {
        float u = v[j];
        float c = 0.7978845608028654f * (u + 0.044715f * u * u * u);
        v[j] = 0.5f * u * (1.0f + tanhf(c));
    }
    ((float4*)(out + (size_t)t * D))[lane] = make_float4(v[0], v[1], v[2], v[3]);
}

// ---------------- launch ----------------
extern "C" void kernel_launch(void* const* d_in, const int* in_sizes, int n_in,
                              void* d_out, int out_size) {
    const float* x     = (const float*)d_in[0];
    const int*   edges = (const int*)  d_in[1];
    const float* W     = (const float*)d_in[2];
    const float* ka    = (const float*)d_in[3];
    const float* ba    = (const float*)d_in[4];
    const float* bias  = (const float*)d_in[5];
    float* out = (float*)d_out;

    (void)in_sizes; (void)n_in; (void)out_size;

    gemm_kernel<<<(N_NODES + 15) / 16, 128>>>(x, W);
    hist_kernel<<<(N_EDGES + 255) / 256, 256>>>(edges);
    offsets_kernel<<<(N_NODES + 255) / 256, 256>>>();
    fill_kernel<<<(N_EDGES + 255) / 256, 256>>>(edges);
    gat_kernel<<<(N_NODES + 7) / 8, 256>>>(ka, ba, bias, out);
}

// round 9
// speedup vs baseline: 1.8604x; 1.0398x over previous
#include <cuda_runtime.h>
#include <math.h>

#define N_NODES 50000
#define N_EDGES 800000
#define D 128
#define HEADS 8
#define UNITS 16

// ---------------- device scratch (zero-initialized at load) ----------------
__device__ float g_xp[N_NODES * D];      // 25.6 MB
__device__ int   g_deg[N_NODES];         // degree per target (self-cleaning: gat resets)
__device__ int   g_off[N_NODES];         // start of target's region in g_esrc
__device__ int   g_cur[N_NODES];         // bump cursor for fill
__device__ int   g_esrc[N_EDGES];        // sources grouped by target (compact CSR)
__device__ int   g_total;                // bump allocator (reset by hist_kernel)

__device__ __forceinline__ float lrelu(float v) {
    return fmaxf(v, 0.2f * v);
}

// ---------------- kernel 1: xp = x @ W — wavefront-minimal ----------------
// 128 threads/block, 16 nodes/block. Transposed smem x tile: xs_t[k][node].
// Per k: 1 LDG.128 (W slice) + 1 broadcast LDS.128 (x) + 16 FFMA  => 5 L1 wf vs 17.
#define XPAD 20                          // 16 nodes padded to 20 floats: 4-way STS conflict,
                                         // keeps float4 (16B) alignment: 80B rows
__global__ void gemm_kernel(const float* __restrict__ x, const float* __restrict__ W) {
    __shared__ float xs_t[D][XPAD];      // 10 KB
    int node0 = blockIdx.x * 16;
    int tid = threadIdx.x;               // 0..127 == k index for the load phase
    int cg = tid & 31;                   // column group: cols [4cg, 4cg+4)
    int ng = tid >> 5;                   // node group:   nodes [4ng, 4ng+4)

    #pragma unroll
    for (int m = 0; m < 16; m++)
        xs_t[tid][m] = x[(node0 + m) * D + tid];      // coalesced LDG, 4-way STS conflict
    __syncthreads();

    const float4* W4 = (const float4*)W;              // W4[k*32 + cg] = W[k][4cg..4cg+3]
    float4 acc0 = make_float4(0.f, 0.f, 0.f, 0.f);
    float4 acc1 = acc0, acc2 = acc0, acc3 = acc0;

    #pragma unroll 8
    for (int k = 0; k < D; k++) {
        float4 w4 = W4[k * 32 + cg];                              // LDG.128, L1-resident
        float4 xv = *(const float4*)&xs_t[k][4 * ng];             // broadcast LDS.128 (1 wf)
        acc0.x += xv.x * w4.x; acc0.y += xv.x * w4.y; acc0.z += xv.x * w4.z; acc0.w += xv.x * w4.w;
        acc1.x += xv.y * w4.x; acc1.y += xv.y * w4.y; acc1.z += xv.y * w4.z; acc1.w += xv.y * w4.w;
        acc2.x += xv.z * w4.x; acc2.y += xv.z * w4.y; acc2.z += xv.z * w4.z; acc2.w += xv.z * w4.w;
        acc3.x += xv.w * w4.x; acc3.y += xv.w * w4.y; acc3.z += xv.w * w4.z; acc3.w += xv.w * w4.w;
    }

    float4* out4 = (float4*)(g_xp + (size_t)(node0 + 4 * ng) * D);   // + col offset below
    out4[0 * 32 + cg] = acc0;            // node 4ng+0, cols [4cg,4cg+4): coalesced 512B/warp
    out4[1 * 32 + cg] = acc1;
    out4[2 * 32 + cg] = acc2;
    out4[3 * 32 + cg] = acc3;
}

// ---------------- kernel 2: degree histogram (R8-exact) ----------------
__global__ void hist_kernel(const int* __restrict__ edges) {
    if (blockIdx.x == 0 && threadIdx.x == 0) g_total = 0;   // consumed by next launch only
    int e = blockIdx.x * blockDim.x + threadIdx.x;
    if (e >= N_EDGES) return;
    int tgt = edges[2 * e + 1];
    atomicAdd(&g_deg[tgt], 1);
}

// ---------------- kernel 3: offsets via warp-aggregated bump alloc (R8-exact) ----------------
__global__ void offsets_kernel() {
    int t = blockIdx.x * blockDim.x + threadIdx.x;
    int lane = threadIdx.x & 31;
    int deg = (t < N_NODES) ? g_deg[t] : 0;

    int incl = deg;
    #pragma unroll
    for (int d = 1; d < 32; d <<= 1) {
        int v = __shfl_up_sync(0xffffffffu, incl, d);
        if (lane >= d) incl += v;
    }
    int total = __shfl_sync(0xffffffffu, incl, 31);
    int base = 0;
    if (lane == 31) base = atomicAdd(&g_total, total);
    base = __shfl_sync(0xffffffffu, base, 31);

    if (t < N_NODES) {
        int off = base + incl - deg;
        g_off[t] = off;
        g_cur[t] = off;
    }
}

// ---------------- kernel 4: scatter sources into per-target regions (R8-exact) ----------------
__global__ void fill_kernel(const int* __restrict__ edges) {
    int e = blockIdx.x * blockDim.x + threadIdx.x;
    if (e >= N_EDGES) return;
    int2 ed = ((const int2*)edges)[e];
    int pos = atomicAdd(&g_cur[ed.y], 1);
    g_esrc[pos] = ed.x;
}

// ---------------- kernel 5: fused GAT pass, warp per target (R8-exact) ----------------
__global__ void gat_kernel(const float* __restrict__ ka,
                           const float* __restrict__ ba,
                           const float* __restrict__ bias,
                           float* __restrict__ out) {
    int t = blockIdx.x * (blockDim.x >> 5) + (threadIdx.x >> 5);
    if (t >= N_NODES) return;
    int lane = threadIdx.x & 31;

    int off = g_off[t];
    int deg = g_deg[t];
    if (lane == 0) g_deg[t] = 0;                 // self-clean for next replay

    float4 k4  = ((const float4*)ka)[lane];
    float4 ba4 = ((const float4*)ba)[lane];
    float4 tb  = ((const float4*)(g_xp + (size_t)t * D))[lane];
    tb.x += 2.0f * ba4.x; tb.y += 2.0f * ba4.y;
    tb.z += 2.0f * ba4.z; tb.w += 2.0f * ba4.w;

    float4 acc = make_float4(0.0f, 0.0f, 0.0f, 0.0f);
    float wsum = 0.0f;

    if (deg > 0) {
        int last = deg - 1;
        const int* __restrict__ srcs = g_esrc + off;

        float4 a0 = ((const float4*)(g_xp + (size_t)srcs[0] * D))[lane];
        float4 a1 = ((const float4*)(g_xp + (size_t)srcs[min(1, last)] * D))[lane];

        for (int i = 0; i < deg; i++) {
            float4 cur = a0;
            a0 = a1;
            int s = srcs[min(i + 2, last)];
            a1 = ((const float4*)(g_xp + (size_t)s * D))[lane];

            float p = lrelu(cur.x + tb.x) * k4.x
                    + lrelu(cur.y + tb.y) * k4.y
                    + lrelu(cur.z + tb.z) * k4.z
                    + lrelu(cur.w + tb.w) * k4.w;
            p += __shfl_xor_sync(0xffffffffu, p, 1);
            p += __shfl_xor_sync(0xffffffffu, p, 2);

            float w = __expf(p);
            wsum  += w;
            acc.x += w * cur.x; acc.y += w * cur.y;
            acc.z += w * cur.z; acc.w += w * cur.w;
        }
    }

    float inv = 1.0f / (wsum + 1e-7f);
    float4 b4 = ((const float4*)bias)[lane];
    float v[4] = { acc.x * inv + b4.x, acc.y * inv + b4.y,
                   acc.z * inv + b4.z, acc.w * inv + b4.w };
    #pragma unroll
    for (int j = 0; j < 4; j++) {
        float u = v[j];
        float c = 0.7978845608028654f * (u + 0.044715f * u * u * u);
        v[j] = 0.5f * u * (1.0f + tanhf(c));
    }
    ((float4*)(out + (size_t)t * D))[lane] = make_float4(v[0], v[1], v[2], v[3]);
}

// ---------------- launch ----------------
extern "C" void kernel_launch(void* const* d_in, const int* in_sizes, int n_in,
                              void* d_out, int out_size) {
    const float* x     = (const float*)d_in[0];
    const int*   edges = (const int*)  d_in[1];
    const float* W     = (const float*)d_in[2];
    const float* ka    = (const float*)d_in[3];
    const float* ba    = (const float*)d_in[4];
    const float* bias  = (const float*)d_in[5];
    float* out = (float*)d_out;

    (void)in_sizes; (void)n_in; (void)out_size;

    gemm_kernel<<<N_NODES / 16, 128>>>(x, W);
    hist_kernel<<<(N_EDGES + 255) / 256, 256>>>(edges);
    offsets_kernel<<<(N_NODES + 255) / 256, 256>>>();
    fill_kernel<<<(N_EDGES + 255) / 256, 256>>>(edges);
    gat_kernel<<<(N_NODES + 7) / 8, 256>>>(ka, ba, bias, out);
}

// round 10
// speedup vs baseline: 2.1021x; 1.1299x over previous
#include <cuda_runtime.h>
#include <math.h>

#define N_NODES 50000
#define N_EDGES 800000
#define D 128
#define HEADS 8
#define UNITS 16

// ---------------- device scratch (zero-initialized at load) ----------------
__device__ float g_xp[N_NODES * D];      // 25.6 MB
__device__ int   g_deg[N_NODES];         // degree per target (self-cleaning: gat resets)
__device__ int   g_off[N_NODES];         // start of target's region in g_esrc
__device__ int   g_cur[N_NODES];         // bump cursor for fill
__device__ int   g_esrc[N_EDGES];        // sources grouped by target (compact CSR)
__device__ int   g_total;                // bump allocator (reset by hist_kernel)

__device__ __forceinline__ float lrelu(float v) {
    return fmaxf(v, 0.2f * v);
}

// ---------------- kernel 1: xp = x @ W — wavefront-minimal (R9-exact) ----------------
#define XPAD 20
__global__ void gemm_kernel(const float* __restrict__ x, const float* __restrict__ W) {
    __shared__ float xs_t[D][XPAD];
    int node0 = blockIdx.x * 16;
    int tid = threadIdx.x;
    int cg = tid & 31;
    int ng = tid >> 5;

    #pragma unroll
    for (int m = 0; m < 16; m++)
        xs_t[tid][m] = x[(node0 + m) * D + tid];
    __syncthreads();

    const float4* W4 = (const float4*)W;
    float4 acc0 = make_float4(0.f, 0.f, 0.f, 0.f);
    float4 acc1 = acc0, acc2 = acc0, acc3 = acc0;

    #pragma unroll 8
    for (int k = 0; k < D; k++) {
        float4 w4 = W4[k * 32 + cg];
        float4 xv = *(const float4*)&xs_t[k][4 * ng];
        acc0.x += xv.x * w4.x; acc0.y += xv.x * w4.y; acc0.z += xv.x * w4.z; acc0.w += xv.x * w4.w;
        acc1.x += xv.y * w4.x; acc1.y += xv.y * w4.y; acc1.z += xv.y * w4.z; acc1.w += xv.y * w4.w;
        acc2.x += xv.z * w4.x; acc2.y += xv.z * w4.y; acc2.z += xv.z * w4.z; acc2.w += xv.z * w4.w;
        acc3.x += xv.w * w4.x; acc3.y += xv.w * w4.y; acc3.z += xv.w * w4.z; acc3.w += xv.w * w4.w;
    }

    float4* out4 = (float4*)(g_xp + (size_t)(node0 + 4 * ng) * D);
    out4[0 * 32 + cg] = acc0;
    out4[1 * 32 + cg] = acc1;
    out4[2 * 32 + cg] = acc2;
    out4[3 * 32 + cg] = acc3;
}

// ---------------- kernel 2: degree histogram (R9-exact) ----------------
__global__ void hist_kernel(const int* __restrict__ edges) {
    if (blockIdx.x == 0 && threadIdx.x == 0) g_total = 0;
    int e = blockIdx.x * blockDim.x + threadIdx.x;
    if (e >= N_EDGES) return;
    int tgt = edges[2 * e + 1];
    atomicAdd(&g_deg[tgt], 1);
}

// ---------------- kernel 3: offsets via warp-aggregated bump alloc (R9-exact) ----------------
__global__ void offsets_kernel() {
    int t = blockIdx.x * blockDim.x + threadIdx.x;
    int lane = threadIdx.x & 31;
    int deg = (t < N_NODES) ? g_deg[t] : 0;

    int incl = deg;
    #pragma unroll
    for (int d = 1; d < 32; d <<= 1) {
        int v = __shfl_up_sync(0xffffffffu, incl, d);
        if (lane >= d) incl += v;
    }
    int total = __shfl_sync(0xffffffffu, incl, 31);
    int base = 0;
    if (lane == 31) base = atomicAdd(&g_total, total);
    base = __shfl_sync(0xffffffffu, base, 31);

    if (t < N_NODES) {
        int off = base + incl - deg;
        g_off[t] = off;
        g_cur[t] = off;
    }
}

// ---------------- kernel 4: scatter sources into per-target regions (R9-exact) ----------------
__global__ void fill_kernel(const int* __restrict__ edges) {
    int e = blockIdx.x * blockDim.x + threadIdx.x;
    if (e >= N_EDGES) return;
    int2 ed = ((const int2*)edges)[e];
    int pos = atomicAdd(&g_cur[ed.y], 1);
    g_esrc[pos] = ed.x;
}

// ---------------- kernel 5: fused GAT pass, warp per target (R9-exact) ----------------
__global__ void gat_kernel(const float* __restrict__ ka,
                           const float* __restrict__ ba,
                           const float* __restrict__ bias,
                           float* __restrict__ out) {
    int t = blockIdx.x * (blockDim.x >> 5) + (threadIdx.x >> 5);
    if (t >= N_NODES) return;
    int lane = threadIdx.x & 31;

    int off = g_off[t];
    int deg = g_deg[t];
    if (lane == 0) g_deg[t] = 0;

    float4 k4  = ((const float4*)ka)[lane];
    float4 ba4 = ((const float4*)ba)[lane];
    float4 tb  = ((const float4*)(g_xp + (size_t)t * D))[lane];
    tb.x += 2.0f * ba4.x; tb.y += 2.0f * ba4.y;
    tb.z += 2.0f * ba4.z; tb.w += 2.0f * ba4.w;

    float4 acc = make_float4(0.0f, 0.0f, 0.0f, 0.0f);
    float wsum = 0.0f;

    if (deg > 0) {
        int last = deg - 1;
        const int* __restrict__ srcs = g_esrc + off;

        float4 a0 = ((const float4*)(g_xp + (size_t)srcs[0] * D))[lane];
        float4 a1 = ((const float4*)(g_xp + (size_t)srcs[min(1, last)] * D))[lane];

        for (int i = 0; i < deg; i++) {
            float4 cur = a0;
            a0 = a1;
            int s = srcs[min(i + 2, last)];
            a1 = ((const float4*)(g_xp + (size_t)s * D))[lane];

            float p = lrelu(cur.x + tb.x) * k4.x
                    + lrelu(cur.y + tb.y) * k4.y
                    + lrelu(cur.z + tb.z) * k4.z
                    + lrelu(cur.w + tb.w) * k4.w;
            p += __shfl_xor_sync(0xffffffffu, p, 1);
            p += __shfl_xor_sync(0xffffffffu, p, 2);

            float w = __expf(p);
            wsum  += w;
            acc.x += w * cur.x; acc.y += w * cur.y;
            acc.z += w * cur.z; acc.w += w * cur.w;
        }
    }

    float inv = 1.0f / (wsum + 1e-7f);
    float4 b4 = ((const float4*)bias)[lane];
    float v[4] = { acc.x * inv + b4.x, acc.y * inv + b4.y,
                   acc.z * inv + b4.z, acc.w * inv + b4.w };
    #pragma unroll
    for (int j = 0; j < 4; j++) {
        float u = v[j];
        float c = 0.7978845608028654f * (u + 0.044715f * u * u * u);
        v[j] = 0.5f * u * (1.0f + tanhf(c));
    }
    ((float4*)(out + (size_t)t * D))[lane] = make_float4(v[0], v[1], v[2], v[3]);
}

// ---------------- launch: fork gemm onto a side stream, join before gat ----------------
extern "C" void kernel_launch(void* const* d_in, const int* in_sizes, int n_in,
                              void* d_out, int out_size) {
    const float* x     = (const float*)d_in[0];
    const int*   edges = (const int*)  d_in[1];
    const float* W     = (const float*)d_in[2];
    const float* ka    = (const float*)d_in[3];
    const float* ba    = (const float*)d_in[4];
    const float* bias  = (const float*)d_in[5];
    float* out = (float*)d_out;

    (void)in_sizes; (void)n_in; (void)out_size;

    // One-time resource creation (handles only — no device memory, identical
    // captured work on every call).
    static cudaStream_t s_side = nullptr;
    static cudaEvent_t  ev_fork = nullptr, ev_join = nullptr;
    if (s_side == nullptr) {
        cudaStreamCreateWithFlags(&s_side, cudaStreamNonBlocking);
        cudaEventCreateWithFlags(&ev_fork, cudaEventDisableTiming);
        cudaEventCreateWithFlags(&ev_join, cudaEventDisableTiming);
    }

    // fork: side stream inherits the capture dependency
    cudaEventRecord(ev_fork, 0);
    cudaStreamWaitEvent(s_side, ev_fork, 0);

    // branch A (side): gemm -> g_xp
    gemm_kernel<<<N_NODES / 16, 128, 0, s_side>>>(x, W);

    // branch B (main): CSR build chain -> g_deg/g_off/g_esrc
    hist_kernel<<<(N_EDGES + 255) / 256, 256>>>(edges);
    offsets_kernel<<<(N_NODES + 255) / 256, 256>>>();
    fill_kernel<<<(N_EDGES + 255) / 256, 256>>>(edges);

    // join: gat needs both branches
    cudaEventRecord(ev_join, s_side);
    cudaStreamWaitEvent(0, ev_join, 0);

    gat_kernel<<<(N_NODES + 7) / 8, 256>>>(ka, ba, bias, out);
}